// round 16
// baseline (speedup 1.0000x reference)
#include <cuda_runtime.h>
#include <cuda_bf16.h>
#include <cstdint>
#include <cstddef>

typedef __nv_bfloat16 bf16;

#define B_ 16
#define T_ 1024
#define P_ 48
#define S_ 12
#define A_ 24
#define D_ 768
#define DS_ 768
#define NROWS 4608   /* B*S*A */
#define SA_ 288      /* S*A rows per batch element */

#define TXT_ROWS 5392   /* 768 para + 16 question + 4608 a_texts */
#define VID_ROWS 20992  /* 16384 video + 4608 a_buttons */

// ---------------- fp32 scratch ------------------------------------------------
__device__ float g_score[B_ * P_];
__device__ float g_part[B_ * 8 * D_];
__device__ float g_vseg[B_ * D_];
__device__ float g_tq[32 * D_];
__device__ float g_pre[B_ * 3072];
__device__ float g_lpart[NROWS * 24];   // deterministic logits partials

// ---------------- bf16 scratch --------------------------------------------------
__device__ bf16 c_tin[4141056];      // [para(768)|question(16)|atx(4608)] x 768
__device__ bf16 c_vin[16121856];     // [video(16384)|abt(4608)] x 768
__device__ bf16 b_wv1[589824], b_wv2[589824], b_wt1[589824], b_wt2[589824];
__device__ bf16 b_wp1[9437184], b_wp2[2359296];
__device__ bf16 b_wih[1769472], b_whh[1769472], b_wq1[589824];
__device__ bf16 b_h1t[4141056];      // text L1 hidden [5392, 768]
__device__ bf16 b_h1[16121856];      // video L1 hidden; reused by fusion L1 out
__device__ bf16 b_svid[B_ * D_];
__device__ bf16 b_stxt[32 * D_];
__device__ bf16 b_comb[7077888];     // [NROWS, 1536] = [at | ab]
__device__ bf16 b_preA[B_ * 2304];
__device__ bf16 b_xall[3538944];
__device__ bf16 b_hseq[147456];
__device__ bf16 b_hnew[3538944];
__device__ bf16 b_gi[10616832];      // [NROWS, 3*DS] bf16
__device__ bf16 b_gh[442368];        // [S*B, 3*DS] bf16

// ============================================================================
// bf16 tensor-core GEMM body: CTA tile 128x128, 8 warps of 64x32 (frozen engine)
// ACT: 0 = +bias[N], 1 = relu(+bias[N]), 2 = relu(+bias[(r/288)*N + n]),
//      3 = logits: partials of relu(acc+bias[N]) . aux  -> C[r*24 + slot]
// N multiple of 128, K multiple of 64, M arbitrary. ldc = C row stride.
// ============================================================================
#define BKH 64
#define SAK 72
#define SWN 136
#define ASZ (128 * SAK)
#define WSZ (BKH * SWN)
#define TG_SMEM ((2 * ASZ + 2 * WSZ) * 2)  /* 71680 bytes */

__device__ __forceinline__ void cp16(uint32_t dst_smem, const void* src, int sz) {
    asm volatile("cp.async.cg.shared.global [%0], [%1], 16, %2;\n" ::"r"(dst_smem),
                 "l"(src), "r"(sz));
}

__device__ __forceinline__ void ldsm4(uint32_t r[4], uint32_t addr) {
    asm volatile("ldmatrix.sync.aligned.m8n8.x4.shared.b16 {%0,%1,%2,%3},[%4];"
                 : "=r"(r[0]), "=r"(r[1]), "=r"(r[2]), "=r"(r[3])
                 : "r"(addr));
}

__device__ __forceinline__ void ldsm4t(uint32_t r[4], uint32_t addr) {
    asm volatile("ldmatrix.sync.aligned.m8n8.x4.trans.shared.b16 {%0,%1,%2,%3},[%4];"
                 : "=r"(r[0]), "=r"(r[1]), "=r"(r[2]), "=r"(r[3])
                 : "r"(addr));
}

__device__ __forceinline__ void mma_bf16(float c[4], const uint32_t a[4],
                                         const uint32_t b[2]) {
    asm volatile(
        "mma.sync.aligned.m16n8k16.row.col.f32.bf16.bf16.f32 "
        "{%0,%1,%2,%3},{%4,%5,%6,%7},{%8,%9},{%0,%1,%2,%3};"
        : "+f"(c[0]), "+f"(c[1]), "+f"(c[2]), "+f"(c[3])
        : "r"(a[0]), "r"(a[1]), "r"(a[2]), "r"(a[3]), "r"(b[0]), "r"(b[1]));
}

__device__ __forceinline__ void store2(float* C, size_t off, float x, float y) {
    *reinterpret_cast<float2*>(C + off) = make_float2(x, y);
}
__device__ __forceinline__ void store2(bf16* C, size_t off, float x, float y) {
    *reinterpret_cast<__nv_bfloat162*>(C + off) =
        __float22bfloat162_rn(make_float2(x, y));
}

template <int ACT, typename OT>
__device__ __forceinline__ void gemm_body(bf16* smh, const bf16* __restrict__ A,
                                          const bf16* __restrict__ W,
                                          const float* __restrict__ bias,
                                          OT* __restrict__ C,
                                          int M, int N, int K, int ldc,
                                          const float* __restrict__ aux) {
    bf16* As = smh;
    bf16* Ws = smh + 2 * ASZ;

    const int tid = threadIdx.x;
    const int lane = tid & 31;
    const int warp = tid >> 5;
    const int warpM = (warp >> 2) * 64;
    const int warpN = (warp & 3) * 32;
    const int rowBase = blockIdx.y * 128;
    const int colBase = blockIdx.x * 128;
    const int KT = K / BKH;

    float acc[4][4][4];
#pragma unroll
    for (int i = 0; i < 4; i++)
#pragma unroll
        for (int j = 0; j < 4; j++)
#pragma unroll
            for (int k = 0; k < 4; k++) acc[i][j][k] = 0.f;

    auto loadTile = [&](int kt, int buf) {
        bf16* ad = As + buf * ASZ;
#pragma unroll
        for (int i = 0; i < 4; i++) {
            int idx = tid + i * 256;
            int row = idx >> 3, oct = idx & 7;
            int grow = rowBase + row;
            int crow = grow < M ? grow : 0;
            const bf16* src = A + (size_t)crow * K + kt * BKH + oct * 8;
            uint32_t d = (uint32_t)__cvta_generic_to_shared(ad + row * SAK + oct * 8);
            cp16(d, src, grow < M ? 16 : 0);
        }
        bf16* wd = Ws + buf * WSZ;
#pragma unroll
        for (int i = 0; i < 4; i++) {
            int idx = tid + i * 256;
            int row = idx >> 4, oct = idx & 15;
            const bf16* src = W + (size_t)(kt * BKH + row) * N + colBase + oct * 8;
            uint32_t d = (uint32_t)__cvta_generic_to_shared(wd + row * SWN + oct * 8);
            cp16(d, src, 16);
        }
    };

    loadTile(0, 0);
    asm volatile("cp.async.commit_group;\n");

    for (int kt = 0; kt < KT; kt++) {
        const int buf = kt & 1;
        if (kt + 1 < KT) {
            loadTile(kt + 1, buf ^ 1);
            asm volatile("cp.async.commit_group;\n");
            asm volatile("cp.async.wait_group 1;\n");
        } else {
            asm volatile("cp.async.wait_group 0;\n");
        }
        __syncthreads();

        const bf16* a_s = As + buf * ASZ;
        const bf16* w_s = Ws + buf * WSZ;

#pragma unroll
        for (int ks = 0; ks < BKH / 16; ks++) {
            const int k0 = ks * 16;
            uint32_t af[4][4], bfr[4][2];
#pragma unroll
            for (int mi = 0; mi < 4; mi++) {
                uint32_t ad = (uint32_t)__cvta_generic_to_shared(
                    a_s + (size_t)(warpM + mi * 16 + (lane & 15)) * SAK + k0 +
                    ((lane >> 4) * 8));
                ldsm4(af[mi], ad);
            }
#pragma unroll
            for (int nb = 0; nb < 2; nb++) {
                uint32_t tmp[4];
                uint32_t wdaddr = (uint32_t)__cvta_generic_to_shared(
                    w_s + (size_t)(k0 + (lane & 15)) * SWN + warpN + nb * 16 +
                    ((lane >> 4) * 8));
                ldsm4t(tmp, wdaddr);
                bfr[2 * nb][0] = tmp[0];
                bfr[2 * nb][1] = tmp[1];
                bfr[2 * nb + 1][0] = tmp[2];
                bfr[2 * nb + 1][1] = tmp[3];
            }
#pragma unroll
            for (int mi = 0; mi < 4; mi++)
#pragma unroll
                for (int ni = 0; ni < 4; ni++) mma_bf16(acc[mi][ni], af[mi], bfr[ni]);
        }
        __syncthreads();
    }

    if (ACT == 3) {
        // fused logits: partial[r] = sum_c relu(acc + bias[c]) * aux[c]
#pragma unroll
        for (int mi = 0; mi < 4; mi++) {
            const int r0 = rowBase + warpM + mi * 16 + (lane >> 2);
            float part0 = 0.f, part8 = 0.f;
#pragma unroll
            for (int ni = 0; ni < 4; ni++) {
                const int c = colBase + warpN + ni * 8 + 2 * (lane & 3);
                const float b0 = bias[c], b1 = bias[c + 1];
                const float w0 = aux[c], w1 = aux[c + 1];
                part0 += fmaxf(acc[mi][ni][0] + b0, 0.f) * w0 +
                         fmaxf(acc[mi][ni][1] + b1, 0.f) * w1;
                part8 += fmaxf(acc[mi][ni][2] + b0, 0.f) * w0 +
                         fmaxf(acc[mi][ni][3] + b1, 0.f) * w1;
            }
            part0 += __shfl_xor_sync(0xffffffffu, part0, 1);
            part0 += __shfl_xor_sync(0xffffffffu, part0, 2);
            part8 += __shfl_xor_sync(0xffffffffu, part8, 1);
            part8 += __shfl_xor_sync(0xffffffffu, part8, 2);
            if ((lane & 3) == 0) {
                const int slot = blockIdx.x * 4 + (warp & 3);
                float* Cf = reinterpret_cast<float*>(C);
                if (r0 < M) Cf[(size_t)r0 * 24 + slot] = part0;
                if (r0 + 8 < M) Cf[(size_t)(r0 + 8) * 24 + slot] = part8;
            }
        }
        return;
    }

#pragma unroll
    for (int mi = 0; mi < 4; mi++) {
        const int r0 = rowBase + warpM + mi * 16 + (lane >> 2);
        const float* br0;
        const float* br8;
        if (ACT == 2) {
            int g0 = r0 / SA_;
            int g8 = (r0 + 8) / SA_;
            if (g0 > B_ - 1) g0 = B_ - 1;
            if (g8 > B_ - 1) g8 = B_ - 1;
            br0 = bias + (size_t)g0 * N;
            br8 = bias + (size_t)g8 * N;
        } else {
            br0 = bias;
            br8 = bias;
        }
#pragma unroll
        for (int ni = 0; ni < 4; ni++) {
            const int c = colBase + warpN + ni * 8 + 2 * (lane & 3);
            float v0 = acc[mi][ni][0] + br0[c];
            float v1 = acc[mi][ni][1] + br0[c + 1];
            float v2 = acc[mi][ni][2] + br8[c];
            float v3 = acc[mi][ni][3] + br8[c + 1];
            if (ACT >= 1) {
                v0 = fmaxf(v0, 0.f); v1 = fmaxf(v1, 0.f);
                v2 = fmaxf(v2, 0.f); v3 = fmaxf(v3, 0.f);
            }
            if (r0 < M) store2(C, (size_t)r0 * ldc + c, v0, v1);
            if (r0 + 8 < M) store2(C, (size_t)(r0 + 8) * ldc + c, v2, v3);
        }
    }
}

template <int ACT, typename OT>
__global__ __launch_bounds__(256, 2) void hgemm(const bf16* __restrict__ A,
                                                const bf16* __restrict__ W,
                                                const float* __restrict__ bias,
                                                OT* __restrict__ C,
                                                int M, int N, int K, int ldc,
                                                const float* __restrict__ aux) {
    extern __shared__ bf16 smh[];
    gemm_body<ACT, OT>(smh, A, W, bias, C, M, N, K, ldc, aux);
}

// dual GEMM: blockIdx.z selects one of two independent problems (shared N,K)
template <typename OT>
struct DualParams {
    const bf16* A[2];
    const bf16* W[2];
    const float* bias[2];
    OT* C[2];
    int M[2];
    int ldc[2];
    int N, K;
};

template <int ACT, typename OT>
__global__ __launch_bounds__(256, 2) void hgemm_dual(DualParams<OT> p) {
    extern __shared__ bf16 smh[];
    const int z = blockIdx.z;
    if ((int)blockIdx.y * 128 >= p.M[z]) return;
    gemm_body<ACT, OT>(smh, p.A[z], p.W[z], p.bias[z], p.C[z], p.M[z], p.N, p.K,
                       p.ldc[z], nullptr);
}

// dual GEMM + fused wred branch on z==2 (independent work overlapped)
template <int ACT, typename OT>
__global__ __launch_bounds__(256, 2) void hgemm_dual_wred(
    DualParams<OT> p, const float* __restrict__ score,
    const int* __restrict__ starts, const int* __restrict__ ends,
    const bf16* __restrict__ h1v, float* __restrict__ part) {
    extern __shared__ bf16 smh[];
    const int z = blockIdx.z;
    if (z < 2) {
        if ((int)blockIdx.y * 128 >= p.M[z]) return;
        gemm_body<ACT, OT>(smh, p.A[z], p.W[z], p.bias[z], p.C[z], p.M[z], p.N,
                           p.K, p.ldc[z], nullptr);
        return;
    }
    // z == 2: segment-weight reduce (8 chunks x 16 batch = 128 blocks)
    int flat = blockIdx.y * gridDim.x + blockIdx.x;
    if (flat >= 128) return;
    int c = flat & 7, b = flat >> 3;
    float* wsh = reinterpret_cast<float*>(smh);  // 128 floats
    int tid = threadIdx.x;
    int tbase = c * 128;
    if (tid < 128) {
        int t = tbase + tid;
        float w = 0.f;
        for (int pp = 0; pp < P_; pp++) {
            int s = starts[b * P_ + pp], e = ends[b * P_ + pp];
            float sc = score[b * P_ + pp];
            if (s >= e) {
                if (t == s) w += sc;
            } else if (t >= s && t < e) {
                w += sc / (float)(e - s);
            }
        }
        wsh[tid] = w;
    }
    __syncthreads();
#pragma unroll
    for (int rep = 0; rep < 3; rep++) {
        int d = tid + rep * 256;
        float acc = 0.f;
        for (int i = 0; i < 128; i++) {
            int t = tbase + i;
            acc += wsh[i] * __bfloat162float(h1v[((size_t)b * T_ + t) * D_ + d]);
        }
        part[((size_t)b * 8 + c) * D_ + d] = acc;
    }
}

// ---------------- fused multi-segment fp32 -> bf16 conversion ------------------
#define NSEG 14
struct CvtSegs {
    const float* src[NSEG];
    bf16* dst[NSEG];
    long long off[NSEG + 1];
};

__global__ void cvt_multi_kernel(CvtSegs s) {
    long long i8 = ((long long)blockIdx.x * blockDim.x + threadIdx.x) * 8;
    if (i8 >= s.off[NSEG]) return;
    int seg = 0;
#pragma unroll
    for (int k = 1; k < NSEG; k++)
        if (i8 >= s.off[k]) seg = k;
    long long local = i8 - s.off[seg];
    const float4* sp = reinterpret_cast<const float4*>(s.src[seg] + local);
    float4 v0 = __ldcs(sp);
    float4 v1 = __ldcs(sp + 1);
    union { __nv_bfloat162 h[4]; uint4 u; } pk;
    pk.h[0] = __float22bfloat162_rn(make_float2(v0.x, v0.y));
    pk.h[1] = __float22bfloat162_rn(make_float2(v0.z, v0.w));
    pk.h[2] = __float22bfloat162_rn(make_float2(v1.x, v1.y));
    pk.h[3] = __float22bfloat162_rn(make_float2(v1.z, v1.w));
    __stcs(reinterpret_cast<uint4*>(s.dst[seg] + local), pk.u);
}

// ---------------- small kernels ----------------------------------------------
__global__ void softmax_paras_kernel(const float* __restrict__ ps,
                                     float* __restrict__ score) {
    int b = threadIdx.x;
    if (b >= B_) return;
    float mx = -1e30f;
    for (int p = 0; p < P_; p++) mx = fmaxf(mx, ps[b * P_ + p]);
    float sum = 0.f;
    for (int p = 0; p < P_; p++) sum += expf(ps[b * P_ + p] - mx);
    float inv = 1.f / sum;
    for (int p = 0; p < P_; p++) score[b * P_ + p] = expf(ps[b * P_ + p] - mx) * inv;
}

// merged vcomb (blocks 0..15) + stxt (blocks 16..31)
__global__ void seg_reduce_kernel(const float* __restrict__ part,
                                  const float* __restrict__ score,
                                  const bf16* __restrict__ h1t,
                                  bf16* __restrict__ svid,
                                  bf16* __restrict__ stxt) {
    int blk = blockIdx.x, d = threadIdx.x;
    if (blk < B_) {
        int b = blk;
        float acc = 0.f;
#pragma unroll
        for (int c = 0; c < 8; c++) acc += part[((size_t)b * 8 + c) * D_ + d];
        svid[b * D_ + d] = __float2bfloat16_rn(acc);
    } else {
        int b = blk - B_;
        float acc = 0.f;
        for (int p = 0; p < P_; p++)
            acc += score[b * P_ + p] *
                   __bfloat162float(h1t[((size_t)(b * P_ + p)) * D_ + d]);
        stxt[b * D_ + d] = __float2bfloat16_rn(acc);
        stxt[(16 + b) * D_ + d] = h1t[(size_t)(768 + b) * D_ + d];
    }
}

__global__ void prea_kernel(const float* __restrict__ vseg,
                            const float* __restrict__ tq,
                            bf16* __restrict__ preA) {
    int b = blockIdx.x, d = threadIdx.x;
    preA[(size_t)b * 2304 + d] = __float2bfloat16_rn(vseg[b * D_ + d]);
    preA[(size_t)b * 2304 + D_ + d] = __float2bfloat16_rn(tq[b * D_ + d]);
    preA[(size_t)b * 2304 + 2 * D_ + d] =
        __float2bfloat16_rn(tq[(size_t)(16 + b) * D_ + d]);
}

__global__ void hseq_kernel(const bf16* __restrict__ xall,
                            const int* __restrict__ label,
                            const float* __restrict__ state0,
                            bf16* __restrict__ hseq) {
    int sb = blockIdx.x;
    int s = sb / B_, b = sb % B_;
    int d = threadIdx.x;
    bf16 v;
    if (s == 0) {
        v = __float2bfloat16_rn(state0[d]);
    } else {
        int lab = label[b * S_ + (s - 1)];
        v = xall[(size_t)((b * S_ + (s - 1)) * A_ + lab) * DS_ + d];
    }
    hseq[(size_t)sb * DS_ + d] = v;
}

__global__ void gru_kernel(const bf16* __restrict__ gi,
                           const bf16* __restrict__ gh,
                           const bf16* __restrict__ hseq,
                           bf16* __restrict__ hnew) {
    int r = blockIdx.x;
    int d = threadIdx.x;
    int bs = r / A_;
    int b = bs / S_, s = bs % S_;
    int sb = s * B_ + b;
    size_t gbase = (size_t)r * (3 * DS_);
    size_t hbase = (size_t)sb * (3 * DS_);
    float ir = __bfloat162float(gi[gbase + d]);
    float iz = __bfloat162float(gi[gbase + DS_ + d]);
    float in = __bfloat162float(gi[gbase + 2 * DS_ + d]);
    float hr = __bfloat162float(gh[hbase + d]);
    float hz = __bfloat162float(gh[hbase + DS_ + d]);
    float hn = __bfloat162float(gh[hbase + 2 * DS_ + d]);
    float h = __bfloat162float(hseq[(size_t)sb * DS_ + d]);
    float rg = 1.f / (1.f + expf(-(ir + hr)));
    float z = 1.f / (1.f + expf(-(iz + hz)));
    float n = tanhf(in + rg * hn);
    hnew[(size_t)r * DS_ + d] = __float2bfloat16_rn((1.f - z) * n + z * h);
}

__global__ void loss_kernel(const float* __restrict__ lpart,
                            const float* __restrict__ bq2,
                            const int* __restrict__ label,
                            float* __restrict__ out) {
    __shared__ float sh[S_ * B_];
    int t = threadIdx.x;
    int b = t / S_, s = t % S_;
    const float bq = bq2[0];
    size_t rbase = (size_t)(b * S_ + s) * A_;
    float l[A_];
#pragma unroll
    for (int a = 0; a < A_; a++) {
        float sum = bq;
        const float* lp = lpart + (rbase + a) * 24;
#pragma unroll
        for (int k = 0; k < 24; k++) sum += lp[k];
        l[a] = sum;
    }
    float mx = -1e30f;
#pragma unroll
    for (int a = 0; a < A_; a++) mx = fmaxf(mx, l[a]);
    float sum = 0.f;
#pragma unroll
    for (int a = 0; a < A_; a++) sum += expf(l[a] - mx);
    float lse = mx + logf(sum);
    int lab = label[b * S_ + s];
    sh[t] = lse - l[lab];
    __syncthreads();
    if (t == 0) {
        float tot = 0.f;
        for (int i = 0; i < S_ * B_; i++) tot += sh[i];
        out[0] = tot / (float)(S_ * B_);
    }
}

// ---------------- launch ------------------------------------------------------
template <typename OT>
static inline void run_gemm(const bf16* A, const bf16* W, const float* bias,
                            OT* C, int M, int N, int K, int act, int ldc = 0,
                            const float* aux = nullptr) {
    if (ldc == 0) ldc = N;
    dim3 grid(N / 128, (M + 127) / 128);
    if (act == 0) {
        cudaFuncSetAttribute(hgemm<0, OT>,
                             cudaFuncAttributeMaxDynamicSharedMemorySize, TG_SMEM);
        hgemm<0, OT><<<grid, 256, TG_SMEM>>>(A, W, bias, C, M, N, K, ldc, aux);
    } else if (act == 1) {
        cudaFuncSetAttribute(hgemm<1, OT>,
                             cudaFuncAttributeMaxDynamicSharedMemorySize, TG_SMEM);
        hgemm<1, OT><<<grid, 256, TG_SMEM>>>(A, W, bias, C, M, N, K, ldc, aux);
    } else if (act == 2) {
        cudaFuncSetAttribute(hgemm<2, OT>,
                             cudaFuncAttributeMaxDynamicSharedMemorySize, TG_SMEM);
        hgemm<2, OT><<<grid, 256, TG_SMEM>>>(A, W, bias, C, M, N, K, ldc, aux);
    } else {
        cudaFuncSetAttribute(hgemm<3, OT>,
                             cudaFuncAttributeMaxDynamicSharedMemorySize, TG_SMEM);
        hgemm<3, OT><<<grid, 256, TG_SMEM>>>(A, W, bias, C, M, N, K, ldc, aux);
    }
}

template <int ACT, typename OT>
static inline void run_gemm_dual(const bf16* A0, const bf16* W0, const float* b0,
                                 OT* C0, int M0, int ldc0,
                                 const bf16* A1, const bf16* W1, const float* b1,
                                 OT* C1, int M1, int ldc1, int N, int K) {
    DualParams<OT> p;
    p.A[0] = A0; p.W[0] = W0; p.bias[0] = b0; p.C[0] = C0; p.M[0] = M0;
    p.ldc[0] = ldc0;
    p.A[1] = A1; p.W[1] = W1; p.bias[1] = b1; p.C[1] = C1; p.M[1] = M1;
    p.ldc[1] = ldc1;
    p.N = N; p.K = K;
    int mMax = M0 > M1 ? M0 : M1;
    dim3 grid(N / 128, (mMax + 127) / 128, 2);
    cudaFuncSetAttribute(hgemm_dual<ACT, OT>,
                         cudaFuncAttributeMaxDynamicSharedMemorySize, TG_SMEM);
    hgemm_dual<ACT, OT><<<grid, 256, TG_SMEM>>>(p);
}

extern "C" void kernel_launch(void* const* d_in, const int* in_sizes, int n_in,
                              void* d_out, int out_size) {
    const float* video = (const float*)d_in[0];
    const float* para = (const float*)d_in[1];
    const float* question = (const float*)d_in[2];
    const float* a_texts = (const float*)d_in[3];
    const float* a_buttons = (const float*)d_in[4];
    const float* paras_score = (const float*)d_in[5];
    const int* starts = (const int*)d_in[6];
    const int* ends = (const int*)d_in[7];
    const int* label = (const int*)d_in[8];
    const float* wv1 = (const float*)d_in[9];
    const float* bv1 = (const float*)d_in[10];
    const float* wv2 = (const float*)d_in[11];
    const float* bv2 = (const float*)d_in[12];
    const float* wt1 = (const float*)d_in[13];
    const float* bt1 = (const float*)d_in[14];
    const float* wt2 = (const float*)d_in[15];
    const float* bt2 = (const float*)d_in[16];
    const float* wp1 = (const float*)d_in[17];
    const float* bp1 = (const float*)d_in[18];
    const float* wp2 = (const float*)d_in[19];
    const float* bp2 = (const float*)d_in[20];
    const float* w_ih = (const float*)d_in[21];
    const float* b_ih = (const float*)d_in[22];
    const float* w_hh = (const float*)d_in[23];
    const float* b_hh = (const float*)d_in[24];
    const float* wq1 = (const float*)d_in[25];
    const float* bq1 = (const float*)d_in[26];
    const float* wq2 = (const float*)d_in[27];
    const float* bq2 = (const float*)d_in[28];
    const float* state0 = (const float*)d_in[29];
    float* out = (float*)d_out;

    float *p_score, *p_part, *p_vseg, *p_tq, *p_pre, *p_lpart;
    cudaGetSymbolAddress((void**)&p_score, g_score);
    cudaGetSymbolAddress((void**)&p_part, g_part);
    cudaGetSymbolAddress((void**)&p_vseg, g_vseg);
    cudaGetSymbolAddress((void**)&p_tq, g_tq);
    cudaGetSymbolAddress((void**)&p_pre, g_pre);
    cudaGetSymbolAddress((void**)&p_lpart, g_lpart);

    bf16 *q_tin, *q_vin;
    bf16 *qw_v1, *qw_v2, *qw_t1, *qw_t2, *qw_p1, *qw_p2, *qw_ih, *qw_hh, *qw_q1;
    bf16 *q_h1t, *q_h1, *q_svid, *q_stxt, *q_comb, *q_preA, *q_xall, *q_hseq,
        *q_hnew, *q_gi, *q_gh;
    cudaGetSymbolAddress((void**)&q_tin, c_tin);
    cudaGetSymbolAddress((void**)&q_vin, c_vin);
    cudaGetSymbolAddress((void**)&qw_v1, b_wv1);
    cudaGetSymbolAddress((void**)&qw_v2, b_wv2);
    cudaGetSymbolAddress((void**)&qw_t1, b_wt1);
    cudaGetSymbolAddress((void**)&qw_t2, b_wt2);
    cudaGetSymbolAddress((void**)&qw_p1, b_wp1);
    cudaGetSymbolAddress((void**)&qw_p2, b_wp2);
    cudaGetSymbolAddress((void**)&qw_ih, b_wih);
    cudaGetSymbolAddress((void**)&qw_hh, b_whh);
    cudaGetSymbolAddress((void**)&qw_q1, b_wq1);
    cudaGetSymbolAddress((void**)&q_h1t, b_h1t);
    cudaGetSymbolAddress((void**)&q_h1, b_h1);
    cudaGetSymbolAddress((void**)&q_svid, b_svid);
    cudaGetSymbolAddress((void**)&q_stxt, b_stxt);
    cudaGetSymbolAddress((void**)&q_comb, b_comb);
    cudaGetSymbolAddress((void**)&q_preA, b_preA);
    cudaGetSymbolAddress((void**)&q_xall, b_xall);
    cudaGetSymbolAddress((void**)&q_hseq, b_hseq);
    cudaGetSymbolAddress((void**)&q_hnew, b_hnew);
    cudaGetSymbolAddress((void**)&q_gi, b_gi);
    cudaGetSymbolAddress((void**)&q_gh, b_gh);

    // 0. single fused fp32 -> bf16 conversion pass (inputs + weights)
    {
        CvtSegs cs;
        const float* srcs[NSEG] = {para, question, a_texts, video, a_buttons,
                                   wv1, wv2, wt1, wt2, wp1, wp2, w_ih, w_hh, wq1};
        bf16* dsts[NSEG] = {q_tin, q_tin + 768 * D_, q_tin + 784 * D_,
                            q_vin, q_vin + (size_t)16384 * D_,
                            qw_v1, qw_v2, qw_t1, qw_t2, qw_p1, qw_p2,
                            qw_ih, qw_hh, qw_q1};
        long long ns[NSEG] = {768 * D_, B_ * D_, NROWS * D_,
                              (long long)B_ * T_ * D_, (long long)NROWS * D_,
                              D_ * D_, D_ * D_, D_ * D_, D_ * D_,
                              (long long)4 * D_ * 4 * D_, (long long)4 * D_ * DS_,
                              (long long)DS_ * 3 * DS_, (long long)DS_ * 3 * DS_,
                              (long long)DS_ * DS_};
        long long acc = 0;
        for (int i = 0; i < NSEG; i++) {
            cs.src[i] = srcs[i];
            cs.dst[i] = dsts[i];
            cs.off[i] = acc;
            acc += ns[i];
        }
        cs.off[NSEG] = acc;
        long long nthreads = acc / 8;
        cvt_multi_kernel<<<(unsigned)((nthreads + 255) / 256), 256>>>(cs);
    }

    // 1. softmax over paragraph scores
    softmax_paras_kernel<<<1, 32>>>(paras_score, p_score);

    // 2. L1 GEMMs batched in ONE launch (text | video)
    run_gemm_dual<1>(q_tin, qw_t1, bt1, q_h1t, TXT_ROWS, D_,
                     q_vin, qw_v1, bv1, q_h1, VID_ROWS, D_, D_, D_);

    // 3. answer L2 GEMMs + independent wred work fused in ONE launch
    {
        DualParams<bf16> p;
        p.A[0] = q_h1t + (size_t)784 * D_; p.W[0] = qw_t2; p.bias[0] = bt2;
        p.C[0] = q_comb; p.M[0] = NROWS; p.ldc[0] = 1536;
        p.A[1] = q_h1 + (size_t)16384 * D_; p.W[1] = qw_v2; p.bias[1] = bv2;
        p.C[1] = q_comb + D_; p.M[1] = NROWS; p.ldc[1] = 1536;
        p.N = D_; p.K = D_;
        dim3 grid(D_ / 128, (NROWS + 127) / 128, 3);
        cudaFuncSetAttribute(hgemm_dual_wred<0, bf16>,
                             cudaFuncAttributeMaxDynamicSharedMemorySize, TG_SMEM);
        hgemm_dual_wred<0, bf16><<<grid, 256, TG_SMEM>>>(p, p_score, starts,
                                                         ends, q_h1, p_part);
    }

    // 4. merged segment reduces
    seg_reduce_kernel<<<2 * B_, D_>>>(p_part, p_score, q_h1t, q_svid, q_stxt);

    // 5. tiny layer-2 GEMMs batched in ONE launch
    run_gemm_dual<0>(q_svid, qw_v2, bv2, p_vseg, B_, D_,
                     q_stxt, qw_t2, bt2, p_tq, 32, D_, D_, D_);

    // 6. fused row bias: preA = [vseg|tseg|q]; pre = preA @ wp1[0:2304] + bp1
    prea_kernel<<<B_, D_>>>(p_vseg, p_tq, q_preA);
    run_gemm(q_preA, qw_p1, bp1, p_pre, B_, 4 * D_, 3 * D_, 0);

    // 7. fusion MLP: layer1 = relu(comb @ wp1[2304:4608] + pre[row/288]) -> h1
    run_gemm(q_comb, qw_p1 + (size_t)(2 * D_) * (4 * D_), p_pre, q_h1,
             NROWS, 4 * D_, 2 * D_, 2);
    run_gemm(q_h1, qw_p2, bp2, q_xall, NROWS, DS_, 4 * D_, 0);

    // 8. teacher-forced hidden states + GRU gate GEMMs batched in ONE launch
    hseq_kernel<<<S_ * B_, DS_>>>(q_xall, label, state0, q_hseq);
    run_gemm_dual<0>(q_xall, qw_ih, b_ih, q_gi, NROWS, 3 * DS_,
                     q_hseq, qw_hh, b_hh, q_gh, S_ * B_, 3 * DS_, 3 * DS_, DS_);
    gru_kernel<<<NROWS, DS_>>>(q_gi, q_gh, q_hseq, q_hnew);

    // 9. fused qh-GEMM + logits partials, then loss
    run_gemm(q_hnew, qw_q1, bq1, p_lpart, NROWS, DS_, DS_, 3, 24, wq2);
    loss_kernel<<<1, S_ * B_>>>(p_lpart, bq2, label, out);
}

// round 17
// speedup vs baseline: 1.0646x; 1.0646x over previous
#include <cuda_runtime.h>
#include <cuda_bf16.h>
#include <cstdint>
#include <cstddef>

typedef __nv_bfloat16 bf16;

#define B_ 16
#define T_ 1024
#define P_ 48
#define S_ 12
#define A_ 24
#define D_ 768
#define DS_ 768
#define NROWS 4608   /* B*S*A */
#define SA_ 288      /* S*A rows per batch element */

#define TXT_ROWS 5392   /* 768 para + 16 question + 4608 a_texts */
#define VID_ROWS 20992  /* 16384 video + 4608 a_buttons */

// ---------------- fp32 scratch ------------------------------------------------
__device__ float g_score[B_ * P_];
__device__ float g_part[B_ * 8 * D_];
__device__ float g_vseg[B_ * D_];
__device__ float g_tq[32 * D_];
__device__ float g_pre[B_ * 3072];
__device__ float g_logits[NROWS];

// ---------------- bf16 scratch --------------------------------------------------
__device__ bf16 c_tin[4141056];      // [para(768)|question(16)|atx(4608)] x 768
__device__ bf16 c_vin[16121856];     // [video(16384)|abt(4608)] x 768
__device__ bf16 b_wv1[589824], b_wv2[589824], b_wt1[589824], b_wt2[589824];
__device__ bf16 b_wp1[9437184], b_wp2[2359296];
__device__ bf16 b_wih[1769472], b_whh[1769472], b_wq1[589824];
__device__ bf16 b_h1t[4141056];      // text L1 hidden [5392, 768]
__device__ bf16 b_h1[16121856];      // video L1 hidden; reused by fusion L1 out
__device__ bf16 b_svid[B_ * D_];
__device__ bf16 b_stxt[32 * D_];
__device__ bf16 b_comb[7077888];     // [NROWS, 1536] = [at | ab]
__device__ bf16 b_preA[B_ * 2304];
__device__ bf16 b_xall[3538944];
__device__ bf16 b_hseq[147456];
__device__ bf16 b_hnew[3538944];
__device__ bf16 b_gi[10616832];      // [NROWS, 3*DS] bf16
__device__ bf16 b_gh[442368];        // [S*B, 3*DS] bf16
__device__ bf16 b_qh[3538944];       // [NROWS, DS] bf16

// ============================================================================
// bf16 tensor-core GEMM body: CTA tile 128x128, 8 warps of 64x32 (frozen engine)
// ACT: 0 = +bias[N], 1 = relu(+bias[N]), 2 = relu(+bias[(r/288)*N + n])
// N multiple of 128, K multiple of 64, M arbitrary. ldc = C row stride.
// ============================================================================
#define BKH 64
#define SAK 72
#define SWN 136
#define ASZ (128 * SAK)
#define WSZ (BKH * SWN)
#define TG_SMEM ((2 * ASZ + 2 * WSZ) * 2)  /* 71680 bytes */

__device__ __forceinline__ void cp16(uint32_t dst_smem, const void* src, int sz) {
    asm volatile("cp.async.cg.shared.global [%0], [%1], 16, %2;\n" ::"r"(dst_smem),
                 "l"(src), "r"(sz));
}

__device__ __forceinline__ void ldsm4(uint32_t r[4], uint32_t addr) {
    asm volatile("ldmatrix.sync.aligned.m8n8.x4.shared.b16 {%0,%1,%2,%3},[%4];"
                 : "=r"(r[0]), "=r"(r[1]), "=r"(r[2]), "=r"(r[3])
                 : "r"(addr));
}

__device__ __forceinline__ void ldsm4t(uint32_t r[4], uint32_t addr) {
    asm volatile("ldmatrix.sync.aligned.m8n8.x4.trans.shared.b16 {%0,%1,%2,%3},[%4];"
                 : "=r"(r[0]), "=r"(r[1]), "=r"(r[2]), "=r"(r[3])
                 : "r"(addr));
}

__device__ __forceinline__ void mma_bf16(float c[4], const uint32_t a[4],
                                         const uint32_t b[2]) {
    asm volatile(
        "mma.sync.aligned.m16n8k16.row.col.f32.bf16.bf16.f32 "
        "{%0,%1,%2,%3},{%4,%5,%6,%7},{%8,%9},{%0,%1,%2,%3};"
        : "+f"(c[0]), "+f"(c[1]), "+f"(c[2]), "+f"(c[3])
        : "r"(a[0]), "r"(a[1]), "r"(a[2]), "r"(a[3]), "r"(b[0]), "r"(b[1]));
}

__device__ __forceinline__ void store2(float* C, size_t off, float x, float y) {
    *reinterpret_cast<float2*>(C + off) = make_float2(x, y);
}
__device__ __forceinline__ void store2(bf16* C, size_t off, float x, float y) {
    *reinterpret_cast<__nv_bfloat162*>(C + off) =
        __float22bfloat162_rn(make_float2(x, y));
}

template <int ACT, typename OT>
__device__ __forceinline__ void gemm_body(bf16* smh, const bf16* __restrict__ A,
                                          const bf16* __restrict__ W,
                                          const float* __restrict__ bias,
                                          OT* __restrict__ C,
                                          int M, int N, int K, int ldc) {
    bf16* As = smh;
    bf16* Ws = smh + 2 * ASZ;

    const int tid = threadIdx.x;
    const int lane = tid & 31;
    const int warp = tid >> 5;
    const int warpM = (warp >> 2) * 64;
    const int warpN = (warp & 3) * 32;
    const int rowBase = blockIdx.y * 128;
    const int colBase = blockIdx.x * 128;
    const int KT = K / BKH;

    float acc[4][4][4];
#pragma unroll
    for (int i = 0; i < 4; i++)
#pragma unroll
        for (int j = 0; j < 4; j++)
#pragma unroll
            for (int k = 0; k < 4; k++) acc[i][j][k] = 0.f;

    auto loadTile = [&](int kt, int buf) {
        bf16* ad = As + buf * ASZ;
#pragma unroll
        for (int i = 0; i < 4; i++) {
            int idx = tid + i * 256;
            int row = idx >> 3, oct = idx & 7;
            int grow = rowBase + row;
            int crow = grow < M ? grow : 0;
            const bf16* src = A + (size_t)crow * K + kt * BKH + oct * 8;
            uint32_t d = (uint32_t)__cvta_generic_to_shared(ad + row * SAK + oct * 8);
            cp16(d, src, grow < M ? 16 : 0);
        }
        bf16* wd = Ws + buf * WSZ;
#pragma unroll
        for (int i = 0; i < 4; i++) {
            int idx = tid + i * 256;
            int row = idx >> 4, oct = idx & 15;
            const bf16* src = W + (size_t)(kt * BKH + row) * N + colBase + oct * 8;
            uint32_t d = (uint32_t)__cvta_generic_to_shared(wd + row * SWN + oct * 8);
            cp16(d, src, 16);
        }
    };

    loadTile(0, 0);
    asm volatile("cp.async.commit_group;\n");

    for (int kt = 0; kt < KT; kt++) {
        const int buf = kt & 1;
        if (kt + 1 < KT) {
            loadTile(kt + 1, buf ^ 1);
            asm volatile("cp.async.commit_group;\n");
            asm volatile("cp.async.wait_group 1;\n");
        } else {
            asm volatile("cp.async.wait_group 0;\n");
        }
        __syncthreads();

        const bf16* a_s = As + buf * ASZ;
        const bf16* w_s = Ws + buf * WSZ;

#pragma unroll
        for (int ks = 0; ks < BKH / 16; ks++) {
            const int k0 = ks * 16;
            uint32_t af[4][4], bfr[4][2];
#pragma unroll
            for (int mi = 0; mi < 4; mi++) {
                uint32_t ad = (uint32_t)__cvta_generic_to_shared(
                    a_s + (size_t)(warpM + mi * 16 + (lane & 15)) * SAK + k0 +
                    ((lane >> 4) * 8));
                ldsm4(af[mi], ad);
            }
#pragma unroll
            for (int nb = 0; nb < 2; nb++) {
                uint32_t tmp[4];
                uint32_t wdaddr = (uint32_t)__cvta_generic_to_shared(
                    w_s + (size_t)(k0 + (lane & 15)) * SWN + warpN + nb * 16 +
                    ((lane >> 4) * 8));
                ldsm4t(tmp, wdaddr);
                bfr[2 * nb][0] = tmp[0];
                bfr[2 * nb][1] = tmp[1];
                bfr[2 * nb + 1][0] = tmp[2];
                bfr[2 * nb + 1][1] = tmp[3];
            }
#pragma unroll
            for (int mi = 0; mi < 4; mi++)
#pragma unroll
                for (int ni = 0; ni < 4; ni++) mma_bf16(acc[mi][ni], af[mi], bfr[ni]);
        }
        __syncthreads();
    }

#pragma unroll
    for (int mi = 0; mi < 4; mi++) {
        const int r0 = rowBase + warpM + mi * 16 + (lane >> 2);
        const float* br0;
        const float* br8;
        if (ACT == 2) {
            int g0 = r0 / SA_;
            int g8 = (r0 + 8) / SA_;
            if (g0 > B_ - 1) g0 = B_ - 1;
            if (g8 > B_ - 1) g8 = B_ - 1;
            br0 = bias + (size_t)g0 * N;
            br8 = bias + (size_t)g8 * N;
        } else {
            br0 = bias;
            br8 = bias;
        }
#pragma unroll
        for (int ni = 0; ni < 4; ni++) {
            const int c = colBase + warpN + ni * 8 + 2 * (lane & 3);
            float v0 = acc[mi][ni][0] + br0[c];
            float v1 = acc[mi][ni][1] + br0[c + 1];
            float v2 = acc[mi][ni][2] + br8[c];
            float v3 = acc[mi][ni][3] + br8[c + 1];
            if (ACT >= 1) {
                v0 = fmaxf(v0, 0.f); v1 = fmaxf(v1, 0.f);
                v2 = fmaxf(v2, 0.f); v3 = fmaxf(v3, 0.f);
            }
            if (r0 < M) store2(C, (size_t)r0 * ldc + c, v0, v1);
            if (r0 + 8 < M) store2(C, (size_t)(r0 + 8) * ldc + c, v2, v3);
        }
    }
}

template <int ACT, typename OT>
__global__ __launch_bounds__(256, 2) void hgemm(const bf16* __restrict__ A,
                                                const bf16* __restrict__ W,
                                                const float* __restrict__ bias,
                                                OT* __restrict__ C,
                                                int M, int N, int K, int ldc) {
    extern __shared__ bf16 smh[];
    gemm_body<ACT, OT>(smh, A, W, bias, C, M, N, K, ldc);
}

// dual GEMM: blockIdx.z selects one of two independent problems (shared N,K)
template <typename OT>
struct DualParams {
    const bf16* A[2];
    const bf16* W[2];
    const float* bias[2];
    OT* C[2];
    int M[2];
    int ldc[2];
    int N, K;
};

template <int ACT, typename OT>
__global__ __launch_bounds__(256, 2) void hgemm_dual(DualParams<OT> p) {
    extern __shared__ bf16 smh[];
    const int z = blockIdx.z;
    if ((int)blockIdx.y * 128 >= p.M[z]) return;
    gemm_body<ACT, OT>(smh, p.A[z], p.W[z], p.bias[z], p.C[z], p.M[z], p.N, p.K,
                       p.ldc[z]);
}

// ---------------- fused multi-segment fp32 -> bf16 conversion ------------------
#define NSEG 14
struct CvtSegs {
    const float* src[NSEG];
    bf16* dst[NSEG];
    long long off[NSEG + 1];
};

__global__ void cvt_multi_kernel(CvtSegs s) {
    long long i8 = ((long long)blockIdx.x * blockDim.x + threadIdx.x) * 8;
    if (i8 >= s.off[NSEG]) return;
    int seg = 0;
#pragma unroll
    for (int k = 1; k < NSEG; k++)
        if (i8 >= s.off[k]) seg = k;
    long long local = i8 - s.off[seg];
    const float4* sp = reinterpret_cast<const float4*>(s.src[seg] + local);
    float4 v0 = __ldcs(sp);
    float4 v1 = __ldcs(sp + 1);
    union { __nv_bfloat162 h[4]; uint4 u; } pk;
    pk.h[0] = __float22bfloat162_rn(make_float2(v0.x, v0.y));
    pk.h[1] = __float22bfloat162_rn(make_float2(v0.z, v0.w));
    pk.h[2] = __float22bfloat162_rn(make_float2(v1.x, v1.y));
    pk.h[3] = __float22bfloat162_rn(make_float2(v1.z, v1.w));
    __stcs(reinterpret_cast<uint4*>(s.dst[seg] + local), pk.u);
}

// ---------------- small kernels ----------------------------------------------
__global__ void softmax_paras_kernel(const float* __restrict__ ps,
                                     float* __restrict__ score) {
    int b = threadIdx.x;
    if (b >= B_) return;
    float mx = -1e30f;
    for (int p = 0; p < P_; p++) mx = fmaxf(mx, ps[b * P_ + p]);
    float sum = 0.f;
    for (int p = 0; p < P_; p++) sum += expf(ps[b * P_ + p] - mx);
    float inv = 1.f / sum;
    for (int p = 0; p < P_; p++) score[b * P_ + p] = expf(ps[b * P_ + p] - mx) * inv;
}

// fused: per-block compute the 128 segment weights for this chunk (smem),
// then weighted-reduce video h1 over the chunk.
__global__ void wred_fused_kernel(const float* __restrict__ score,
                                  const int* __restrict__ starts,
                                  const int* __restrict__ ends,
                                  const bf16* __restrict__ h1v,
                                  float* __restrict__ part) {
    __shared__ float wsh[128];
    int c = blockIdx.x, b = blockIdx.y, d = threadIdx.x;
    int tbase = c * 128;
    if (d < 128) {
        int t = tbase + d;
        float w = 0.f;
        for (int p = 0; p < P_; p++) {
            int s = starts[b * P_ + p], e = ends[b * P_ + p];
            float sc = score[b * P_ + p];
            if (s >= e) {
                if (t == s) w += sc;
            } else if (t >= s && t < e) {
                w += sc / (float)(e - s);
            }
        }
        wsh[d] = w;
    }
    __syncthreads();
    float acc = 0.f;
    for (int i = 0; i < 128; i++) {
        int t = tbase + i;
        acc += wsh[i] * __bfloat162float(h1v[((size_t)b * T_ + t) * D_ + d]);
    }
    part[((size_t)b * 8 + c) * D_ + d] = acc;
}

// merged vcomb (blocks 0..15) + stxt (blocks 16..31)
__global__ void seg_reduce_kernel(const float* __restrict__ part,
                                  const float* __restrict__ score,
                                  const bf16* __restrict__ h1t,
                                  bf16* __restrict__ svid,
                                  bf16* __restrict__ stxt) {
    int blk = blockIdx.x, d = threadIdx.x;
    if (blk < B_) {
        int b = blk;
        float acc = 0.f;
#pragma unroll
        for (int c = 0; c < 8; c++) acc += part[((size_t)b * 8 + c) * D_ + d];
        svid[b * D_ + d] = __float2bfloat16_rn(acc);
    } else {
        int b = blk - B_;
        float acc = 0.f;
        for (int p = 0; p < P_; p++)
            acc += score[b * P_ + p] *
                   __bfloat162float(h1t[((size_t)(b * P_ + p)) * D_ + d]);
        stxt[b * D_ + d] = __float2bfloat16_rn(acc);
        stxt[(16 + b) * D_ + d] = h1t[(size_t)(768 + b) * D_ + d];
    }
}

__global__ void prea_kernel(const float* __restrict__ vseg,
                            const float* __restrict__ tq,
                            bf16* __restrict__ preA) {
    int b = blockIdx.x, d = threadIdx.x;
    preA[(size_t)b * 2304 + d] = __float2bfloat16_rn(vseg[b * D_ + d]);
    preA[(size_t)b * 2304 + D_ + d] = __float2bfloat16_rn(tq[b * D_ + d]);
    preA[(size_t)b * 2304 + 2 * D_ + d] =
        __float2bfloat16_rn(tq[(size_t)(16 + b) * D_ + d]);
}

__global__ void hseq_kernel(const bf16* __restrict__ xall,
                            const int* __restrict__ label,
                            const float* __restrict__ state0,
                            bf16* __restrict__ hseq) {
    int sb = blockIdx.x;
    int s = sb / B_, b = sb % B_;
    int d = threadIdx.x;
    bf16 v;
    if (s == 0) {
        v = __float2bfloat16_rn(state0[d]);
    } else {
        int lab = label[b * S_ + (s - 1)];
        v = xall[(size_t)((b * S_ + (s - 1)) * A_ + lab) * DS_ + d];
    }
    hseq[(size_t)sb * DS_ + d] = v;
}

__global__ void gru_kernel(const bf16* __restrict__ gi,
                           const bf16* __restrict__ gh,
                           const bf16* __restrict__ hseq,
                           bf16* __restrict__ hnew) {
    int r = blockIdx.x;
    int d = threadIdx.x;
    int bs = r / A_;
    int b = bs / S_, s = bs % S_;
    int sb = s * B_ + b;
    size_t gbase = (size_t)r * (3 * DS_);
    size_t hbase = (size_t)sb * (3 * DS_);
    float ir = __bfloat162float(gi[gbase + d]);
    float iz = __bfloat162float(gi[gbase + DS_ + d]);
    float in = __bfloat162float(gi[gbase + 2 * DS_ + d]);
    float hr = __bfloat162float(gh[hbase + d]);
    float hz = __bfloat162float(gh[hbase + DS_ + d]);
    float hn = __bfloat162float(gh[hbase + 2 * DS_ + d]);
    float h = __bfloat162float(hseq[(size_t)sb * DS_ + d]);
    float rg = 1.f / (1.f + expf(-(ir + hr)));
    float z = 1.f / (1.f + expf(-(iz + hz)));
    float n = tanhf(in + rg * hn);
    hnew[(size_t)r * DS_ + d] = __float2bfloat16_rn((1.f - z) * n + z * h);
}

__global__ void logits_kernel(const bf16* __restrict__ qh,
                              const float* __restrict__ wq2,
                              const float* __restrict__ bq2,
                              float* __restrict__ logits) {
    int warp = (blockIdx.x * blockDim.x + threadIdx.x) >> 5;
    int lane = threadIdx.x & 31;
    if (warp >= NROWS) return;
    float sum = 0.f;
    for (int d = lane; d < DS_; d += 32)
        sum += __bfloat162float(qh[(size_t)warp * DS_ + d]) * wq2[d];
#pragma unroll
    for (int o = 16; o; o >>= 1) sum += __shfl_down_sync(0xffffffffu, sum, o);
    if (lane == 0) logits[warp] = sum + bq2[0];
}

__global__ void loss_kernel(const float* __restrict__ logits,
                            const int* __restrict__ label,
                            float* __restrict__ out) {
    __shared__ float sh[S_ * B_];
    int t = threadIdx.x;
    int b = t / S_, s = t % S_;
    const float* l = &logits[(size_t)(b * S_ + s) * A_];
    float mx = -1e30f;
    for (int a = 0; a < A_; a++) mx = fmaxf(mx, l[a]);
    float sum = 0.f;
    for (int a = 0; a < A_; a++) sum += expf(l[a] - mx);
    float lse = mx + logf(sum);
    int lab = label[b * S_ + s];
    sh[t] = lse - l[lab];
    __syncthreads();
    if (t == 0) {
        float tot = 0.f;
        for (int i = 0; i < S_ * B_; i++) tot += sh[i];
        out[0] = tot / (float)(S_ * B_);
    }
}

// ---------------- launch ------------------------------------------------------
template <typename OT>
static inline void run_gemm(const bf16* A, const bf16* W, const float* bias,
                            OT* C, int M, int N, int K, int act, int ldc = 0) {
    if (ldc == 0) ldc = N;
    dim3 grid(N / 128, (M + 127) / 128);
    if (act == 0) {
        cudaFuncSetAttribute(hgemm<0, OT>,
                             cudaFuncAttributeMaxDynamicSharedMemorySize, TG_SMEM);
        hgemm<0, OT><<<grid, 256, TG_SMEM>>>(A, W, bias, C, M, N, K, ldc);
    } else if (act == 1) {
        cudaFuncSetAttribute(hgemm<1, OT>,
                             cudaFuncAttributeMaxDynamicSharedMemorySize, TG_SMEM);
        hgemm<1, OT><<<grid, 256, TG_SMEM>>>(A, W, bias, C, M, N, K, ldc);
    } else {
        cudaFuncSetAttribute(hgemm<2, OT>,
                             cudaFuncAttributeMaxDynamicSharedMemorySize, TG_SMEM);
        hgemm<2, OT><<<grid, 256, TG_SMEM>>>(A, W, bias, C, M, N, K, ldc);
    }
}

template <int ACT, typename OT>
static inline void run_gemm_dual(const bf16* A0, const bf16* W0, const float* b0,
                                 OT* C0, int M0, int ldc0,
                                 const bf16* A1, const bf16* W1, const float* b1,
                                 OT* C1, int M1, int ldc1, int N, int K) {
    DualParams<OT> p;
    p.A[0] = A0; p.W[0] = W0; p.bias[0] = b0; p.C[0] = C0; p.M[0] = M0;
    p.ldc[0] = ldc0;
    p.A[1] = A1; p.W[1] = W1; p.bias[1] = b1; p.C[1] = C1; p.M[1] = M1;
    p.ldc[1] = ldc1;
    p.N = N; p.K = K;
    int mMax = M0 > M1 ? M0 : M1;
    dim3 grid(N / 128, (mMax + 127) / 128, 2);
    cudaFuncSetAttribute(hgemm_dual<ACT, OT>,
                         cudaFuncAttributeMaxDynamicSharedMemorySize, TG_SMEM);
    hgemm_dual<ACT, OT><<<grid, 256, TG_SMEM>>>(p);
}

extern "C" void kernel_launch(void* const* d_in, const int* in_sizes, int n_in,
                              void* d_out, int out_size) {
    const float* video = (const float*)d_in[0];
    const float* para = (const float*)d_in[1];
    const float* question = (const float*)d_in[2];
    const float* a_texts = (const float*)d_in[3];
    const float* a_buttons = (const float*)d_in[4];
    const float* paras_score = (const float*)d_in[5];
    const int* starts = (const int*)d_in[6];
    const int* ends = (const int*)d_in[7];
    const int* label = (const int*)d_in[8];
    const float* wv1 = (const float*)d_in[9];
    const float* bv1 = (const float*)d_in[10];
    const float* wv2 = (const float*)d_in[11];
    const float* bv2 = (const float*)d_in[12];
    const float* wt1 = (const float*)d_in[13];
    const float* bt1 = (const float*)d_in[14];
    const float* wt2 = (const float*)d_in[15];
    const float* bt2 = (const float*)d_in[16];
    const float* wp1 = (const float*)d_in[17];
    const float* bp1 = (const float*)d_in[18];
    const float* wp2 = (const float*)d_in[19];
    const float* bp2 = (const float*)d_in[20];
    const float* w_ih = (const float*)d_in[21];
    const float* b_ih = (const float*)d_in[22];
    const float* w_hh = (const float*)d_in[23];
    const float* b_hh = (const float*)d_in[24];
    const float* wq1 = (const float*)d_in[25];
    const float* bq1 = (const float*)d_in[26];
    const float* wq2 = (const float*)d_in[27];
    const float* bq2 = (const float*)d_in[28];
    const float* state0 = (const float*)d_in[29];
    float* out = (float*)d_out;

    float *p_score, *p_part, *p_vseg, *p_tq, *p_pre, *p_logits;
    cudaGetSymbolAddress((void**)&p_score, g_score);
    cudaGetSymbolAddress((void**)&p_part, g_part);
    cudaGetSymbolAddress((void**)&p_vseg, g_vseg);
    cudaGetSymbolAddress((void**)&p_tq, g_tq);
    cudaGetSymbolAddress((void**)&p_pre, g_pre);
    cudaGetSymbolAddress((void**)&p_logits, g_logits);

    bf16 *q_tin, *q_vin;
    bf16 *qw_v1, *qw_v2, *qw_t1, *qw_t2, *qw_p1, *qw_p2, *qw_ih, *qw_hh, *qw_q1;
    bf16 *q_h1t, *q_h1, *q_svid, *q_stxt, *q_comb, *q_preA, *q_xall, *q_hseq,
        *q_hnew, *q_gi, *q_gh, *q_qh;
    cudaGetSymbolAddress((void**)&q_tin, c_tin);
    cudaGetSymbolAddress((void**)&q_vin, c_vin);
    cudaGetSymbolAddress((void**)&qw_v1, b_wv1);
    cudaGetSymbolAddress((void**)&qw_v2, b_wv2);
    cudaGetSymbolAddress((void**)&qw_t1, b_wt1);
    cudaGetSymbolAddress((void**)&qw_t2, b_wt2);
    cudaGetSymbolAddress((void**)&qw_p1, b_wp1);
    cudaGetSymbolAddress((void**)&qw_p2, b_wp2);
    cudaGetSymbolAddress((void**)&qw_ih, b_wih);
    cudaGetSymbolAddress((void**)&qw_hh, b_whh);
    cudaGetSymbolAddress((void**)&qw_q1, b_wq1);
    cudaGetSymbolAddress((void**)&q_h1t, b_h1t);
    cudaGetSymbolAddress((void**)&q_h1, b_h1);
    cudaGetSymbolAddress((void**)&q_svid, b_svid);
    cudaGetSymbolAddress((void**)&q_stxt, b_stxt);
    cudaGetSymbolAddress((void**)&q_comb, b_comb);
    cudaGetSymbolAddress((void**)&q_preA, b_preA);
    cudaGetSymbolAddress((void**)&q_xall, b_xall);
    cudaGetSymbolAddress((void**)&q_hseq, b_hseq);
    cudaGetSymbolAddress((void**)&q_hnew, b_hnew);
    cudaGetSymbolAddress((void**)&q_gi, b_gi);
    cudaGetSymbolAddress((void**)&q_gh, b_gh);
    cudaGetSymbolAddress((void**)&q_qh, b_qh);

    // 0. single fused fp32 -> bf16 conversion pass (inputs + weights)
    {
        CvtSegs cs;
        const float* srcs[NSEG] = {para, question, a_texts, video, a_buttons,
                                   wv1, wv2, wt1, wt2, wp1, wp2, w_ih, w_hh, wq1};
        bf16* dsts[NSEG] = {q_tin, q_tin + 768 * D_, q_tin + 784 * D_,
                            q_vin, q_vin + (size_t)16384 * D_,
                            qw_v1, qw_v2, qw_t1, qw_t2, qw_p1, qw_p2,
                            qw_ih, qw_hh, qw_q1};
        long long ns[NSEG] = {768 * D_, B_ * D_, NROWS * D_,
                              (long long)B_ * T_ * D_, (long long)NROWS * D_,
                              D_ * D_, D_ * D_, D_ * D_, D_ * D_,
                              (long long)4 * D_ * 4 * D_, (long long)4 * D_ * DS_,
                              (long long)DS_ * 3 * DS_, (long long)DS_ * 3 * DS_,
                              (long long)DS_ * DS_};
        long long acc = 0;
        for (int i = 0; i < NSEG; i++) {
            cs.src[i] = srcs[i];
            cs.dst[i] = dsts[i];
            cs.off[i] = acc;
            acc += ns[i];
        }
        cs.off[NSEG] = acc;
        long long nthreads = acc / 8;
        cvt_multi_kernel<<<(unsigned)((nthreads + 255) / 256), 256>>>(cs);
    }

    // 1. softmax over paragraph scores
    softmax_paras_kernel<<<1, 32>>>(paras_score, p_score);

    // 2. L1 GEMMs batched in ONE launch (text | video)
    run_gemm_dual<1>(q_tin, qw_t1, bt1, q_h1t, TXT_ROWS, D_,
                     q_vin, qw_v1, bv1, q_h1, VID_ROWS, D_, D_, D_);

    // 3. answer L2 GEMMs batched in ONE launch (at | ab -> comb)
    run_gemm_dual<0>(q_h1t + (size_t)784 * D_, qw_t2, bt2, q_comb, NROWS, 1536,
                     q_h1 + (size_t)16384 * D_, qw_v2, bv2, q_comb + D_, NROWS,
                     1536, D_, D_);

    // 4. fused segment-weight reduce (wts folded into wred) + merged reduces
    wred_fused_kernel<<<dim3(8, B_), D_>>>(p_score, starts, ends, q_h1, p_part);
    seg_reduce_kernel<<<2 * B_, D_>>>(p_part, p_score, q_h1t, q_svid, q_stxt);

    // 5. tiny layer-2 GEMMs batched in ONE launch
    run_gemm_dual<0>(q_svid, qw_v2, bv2, p_vseg, B_, D_,
                     q_stxt, qw_t2, bt2, p_tq, 32, D_, D_, D_);

    // 6. fused row bias: preA = [vseg|tseg|q]; pre = preA @ wp1[0:2304] + bp1
    prea_kernel<<<B_, D_>>>(p_vseg, p_tq, q_preA);
    run_gemm(q_preA, qw_p1, bp1, p_pre, B_, 4 * D_, 3 * D_, 0);

    // 7. fusion MLP: layer1 = relu(comb @ wp1[2304:4608] + pre[row/288]) -> h1
    run_gemm(q_comb, qw_p1 + (size_t)(2 * D_) * (4 * D_), p_pre, q_h1,
             NROWS, 4 * D_, 2 * D_, 2);
    run_gemm(q_h1, qw_p2, bp2, q_xall, NROWS, DS_, 4 * D_, 0);

    // 8. teacher-forced hidden states + GRU gate GEMMs batched in ONE launch
    hseq_kernel<<<S_ * B_, DS_>>>(q_xall, label, state0, q_hseq);
    run_gemm_dual<0>(q_xall, qw_ih, b_ih, q_gi, NROWS, 3 * DS_,
                     q_hseq, qw_hh, b_hh, q_gh, S_ * B_, 3 * DS_, 3 * DS_, DS_);
    gru_kernel<<<NROWS, DS_>>>(q_gi, q_gh, q_hseq, q_hnew);

    // 9. logits MLP + loss (qh stored bf16)
    run_gemm(q_hnew, qw_q1, bq1, q_qh, NROWS, DS_, DS_, 1);
    logits_kernel<<<(NROWS * 32 + 255) / 256, 256>>>(q_qh, wq2, bq2, p_logits);
    loss_kernel<<<1, S_ * B_>>>(p_logits, label, out);
}